// round 14
// baseline (speedup 1.0000x reference)
#include <cuda_runtime.h>
#include <math.h>
#include <stddef.h>

#define N_NODE 40000
#define EMB    100
#define CH     25        // float4 chunks per embedding row
#define B      512
#define L      50
#define NN     50
#define E_EDGES 800000
#define FULLM  0xffffffffu

// ---- scratch: device globals, referenced ONLY from device code -------------
__device__ __align__(16) float g_x1[N_NODE * EMB];
__device__ __align__(16) float g_x2[N_NODE * EMB];
__device__ __align__(16) float g_e1t[(N_NODE + 1) * EMB];  // row0 zeros, 1.. = emb_gnn
__device__ __align__(16) float g_h[B * NN * EMB];
__device__ __align__(16) float g_seq[B * L * EMB];
__device__ __align__(16) float g_hs[B * EMB];
__device__ __align__(16) float g_posw[L * EMB];            // pos@w1W[:, :100].T + w1b
__device__ __align__(16) float g_sel[B * EMB];
__device__ __align__(16) float g_s1[B * EMB];
__device__ __align__(16) float g_s2[B * EMB];
__device__ __align__(16) float g_self[B * EMB];
__device__ float g_lse[B];

// CSR scratch
__device__ int   g_cnt[N_NODE];
__device__ int   g_off[N_NODE + 1];
__device__ int   g_pos[N_NODE];
__device__ int   g_ecol[E_EDGES];
__device__ float g_eval[E_EDGES];

__device__ __forceinline__ float wredsum(float v) {
    #pragma unroll
    for (int o = 16; o; o >>= 1) v += __shfl_xor_sync(FULLM, v, o);
    return v;
}
__device__ __forceinline__ float wredmax(float v) {
    #pragma unroll
    for (int o = 16; o; o >>= 1) v = fmaxf(v, __shfl_xor_sync(FULLM, v, o));
    return v;
}

// ---------------- 0. zero: CSR counters + e1t row 0 --------------------------
__global__ void k_zero() {
    int i = blockIdx.x * blockDim.x + threadIdx.x;
    if (i < N_NODE) g_cnt[i] = 0;
    if (i < EMB) g_e1t[i] = 0.f;
}

// ---------------- 1a. histogram of row ids -----------------------------------
__global__ void k_hist(const int* __restrict__ rows) {
    int e = blockIdx.x * blockDim.x + threadIdx.x;
    if (e < E_EDGES) atomicAdd(&g_cnt[rows[e]], 1);
}

// ---------------- 1b. exclusive scan (single block) ---------------------------
#define NT_SCAN 1024
#define SCHUNK ((N_NODE + NT_SCAN - 1) / NT_SCAN)   // 40
__global__ void k_scan() {
    __shared__ int ps[NT_SCAN];
    int t = threadIdx.x;
    int base = t * SCHUNK;
    int s = 0;
    for (int i = 0; i < SCHUNK; i++) {
        int idx = base + i;
        if (idx < N_NODE) s += g_cnt[idx];
    }
    ps[t] = s;
    __syncthreads();
    for (int o = 1; o < NT_SCAN; o <<= 1) {
        int v = (t >= o) ? ps[t - o] : 0;
        __syncthreads();
        ps[t] += v;
        __syncthreads();
    }
    int run = (t > 0) ? ps[t - 1] : 0;
    for (int i = 0; i < SCHUNK; i++) {
        int idx = base + i;
        if (idx < N_NODE) {
            int c = g_cnt[idx];
            g_off[idx] = run;
            g_pos[idx] = run;
            run += c;
        }
    }
    if (t == NT_SCAN - 1) g_off[N_NODE] = run;
}

// ---------------- 1c. scatter edges into row-sorted order ---------------------
__global__ void k_scatter(const int* __restrict__ rows, const int* __restrict__ cols,
                          const float* __restrict__ vals) {
    int e = blockIdx.x * blockDim.x + threadIdx.x;
    if (e >= E_EDGES) return;
    int p = atomicAdd(&g_pos[rows[e]], 1);
    g_ecol[p] = cols[e];
    g_eval[p] = vals[e];
}

// ---------------- 2. SpMM: warp/row, coalesced edge meta, 4-wide MLP gathers ---
__device__ __forceinline__ void spmm_row(const float* __restrict__ in,
                                         float* __restrict__ out,
                                         int row, int lane) {
    int s = g_off[row], e = g_off[row + 1];
    float4 acc = {0.f, 0.f, 0.f, 0.f};
    for (int base = s; base < e; base += 32) {
        int n = e - base; if (n > 32) n = 32;
        // one coalesced read of up to 32 edge (col, val) pairs
        int   c = (lane < n) ? g_ecol[base + lane] : g_ecol[base];
        float v = (lane < n) ? g_eval[base + lane] : 0.f;
        for (int j = 0; j < n; j += 4) {
            int   c0 = __shfl_sync(FULLM, c, j);
            int   c1 = __shfl_sync(FULLM, c, j + 1);
            int   c2 = __shfl_sync(FULLM, c, j + 2);
            int   c3 = __shfl_sync(FULLM, c, j + 3);
            float v0 = __shfl_sync(FULLM, v, j);
            float v1 = __shfl_sync(FULLM, v, j + 1);
            float v2 = __shfl_sync(FULLM, v, j + 2);
            float v3 = __shfl_sync(FULLM, v, j + 3);
            if (lane < CH) {
                float4 x0 = ((const float4*)in)[c0 * CH + lane];
                float4 x1 = ((const float4*)in)[c1 * CH + lane];
                float4 x2 = ((const float4*)in)[c2 * CH + lane];
                float4 x3 = ((const float4*)in)[c3 * CH + lane];
                acc.x += v0 * x0.x; acc.y += v0 * x0.y; acc.z += v0 * x0.z; acc.w += v0 * x0.w;
                acc.x += v1 * x1.x; acc.y += v1 * x1.y; acc.z += v1 * x1.z; acc.w += v1 * x1.w;
                acc.x += v2 * x2.x; acc.y += v2 * x2.y; acc.z += v2 * x2.z; acc.w += v2 * x2.w;
                acc.x += v3 * x3.x; acc.y += v3 * x3.y; acc.z += v3 * x3.z; acc.w += v3 * x3.w;
            }
        }
    }
    if (lane < CH) ((float4*)out)[row * CH + lane] = acc;
}
__global__ void k_spmm_csr1(const float* __restrict__ in) {
    int wid  = (blockIdx.x * blockDim.x + threadIdx.x) >> 5;
    int lane = threadIdx.x & 31;
    if (wid < N_NODE) spmm_row(in, g_x1, wid, lane);
}
__global__ void k_spmm_csr2() {
    int wid  = (blockIdx.x * blockDim.x + threadIdx.x) >> 5;
    int lane = threadIdx.x & 31;
    if (wid < N_NODE) spmm_row(g_x1, g_x2, wid, lane);
}

// ---------------- 3. per-node l2norm + weighted sum -> e1t[1..] --------------
__global__ void k_combine_item(const float* __restrict__ emb, const float* __restrict__ bw) {
    int wid  = (blockIdx.x * blockDim.x + threadIdx.x) >> 5;
    int lane = threadIdx.x & 31;
    if (wid >= N_NODE) return;
    float4 a = {0.f,0.f,0.f,0.f}, bb = a, cc = a;
    if (lane < CH) {
        a  = ((const float4*)emb )[wid * CH + lane];
        bb = ((const float4*)g_x1)[wid * CH + lane];
        cc = ((const float4*)g_x2)[wid * CH + lane];
    }
    float s0 = a.x*a.x + a.y*a.y + a.z*a.z + a.w*a.w;
    float s1 = bb.x*bb.x + bb.y*bb.y + bb.z*bb.z + bb.w*bb.w;
    float s2 = cc.x*cc.x + cc.y*cc.y + cc.z*cc.z + cc.w*cc.w;
    s0 = wredsum(s0); s1 = wredsum(s1); s2 = wredsum(s2);
    float i0 = bw[0] / fmaxf(sqrtf(s0), 1e-12f);
    float i1 = bw[1] / fmaxf(sqrtf(s1), 1e-12f);
    float i2 = bw[2] / fmaxf(sqrtf(s2), 1e-12f);
    if (lane < CH) {
        float4 r;
        r.x = a.x*i0 + bb.x*i1 + cc.x*i2;
        r.y = a.y*i0 + bb.y*i1 + cc.y*i2;
        r.z = a.z*i0 + bb.z*i1 + cc.z*i2;
        r.w = a.w*i0 + bb.w*i1 + cc.w*i2;
        ((float4*)g_e1t)[(wid + 1) * CH + lane] = r;
    }
}

// ---------------- 4. posw[l][o] = pos[l] . w1W[o, :100] + w1b[o] -------------
__global__ void k_posw(const float* __restrict__ pos, const float* __restrict__ w1W,
                       const float* __restrict__ w1b) {
    int gw   = (blockIdx.x * blockDim.x + threadIdx.x) >> 5;
    int lane = threadIdx.x & 31;
    if (gw >= L * EMB) return;
    int l = gw / EMB, o = gw % EMB;
    const float* wr = w1W + o * 2 * EMB;
    float acc = 0.f;
    for (int k = lane; k < EMB; k += 32) acc += pos[l * EMB + k] * wr[k];
    acc = wredsum(acc);
    if (lane == 0) g_posw[l * EMB + o] = acc + w1b[o];
}

// ---------------- 5. GAT per batch element (padded shared) -------------------
__global__ void k_gat(const int* __restrict__ items, const int* __restrict__ adj,
                      const float* __restrict__ a0, const float* __restrict__ a1,
                      const float* __restrict__ a2, const float* __restrict__ a3) {
    __shared__ float sh[NN][EMB + 1];
    __shared__ float sa[4][EMB + 1];
    __shared__ float se[NN][NN];
    __shared__ int   sit[NN];
    int b = blockIdx.x, t = threadIdx.x, nt = blockDim.x;
    for (int i = t; i < NN; i += nt) sit[i] = items[b * NN + i];
    for (int i = t; i < EMB; i += nt) {
        sa[0][i] = a0[i]; sa[1][i] = a1[i]; sa[2][i] = a2[i]; sa[3][i] = a3[i];
    }
    __syncthreads();
    for (int p = t; p < NN * EMB; p += nt)
        sh[p / EMB][p % EMB] = g_e1t[sit[p / EMB] * EMB + p % EMB];
    __syncthreads();
    for (int p = t; p < NN * NN; p += nt) {
        int i = p / NN, j = p % NN;
        int av = adj[b * NN * NN + p];
        float ev;
        if (av >= 1 && av <= 4) {
            const float* ak = sa[av - 1];
            float acc = 0.f;
            #pragma unroll 4
            for (int d = 0; d < EMB; d++) acc += sh[i][d] * ak[d] * sh[j][d];
            ev = acc > 0.f ? acc : 0.2f * acc;
        } else ev = -9e15f;
        se[i][j] = ev;
    }
    __syncthreads();
    int w = t >> 5, lane = t & 31, nw = nt >> 5;
    for (int i = w; i < NN; i += nw) {
        float m = -INFINITY;
        for (int j = lane; j < NN; j += 32) m = fmaxf(m, se[i][j]);
        m = wredmax(m);
        float s = 0.f;
        for (int j = lane; j < NN; j += 32) { float ex = expf(se[i][j] - m); se[i][j] = ex; s += ex; }
        s = wredsum(s);
        float inv = 1.f / s;
        for (int j = lane; j < NN; j += 32) se[i][j] *= inv;
    }
    __syncthreads();
    for (int p = t; p < NN * EMB; p += nt) {
        int i = p / EMB, d = p % EMB;
        float acc = 0.f;
        #pragma unroll 5
        for (int j = 0; j < NN; j++) acc += se[i][j] * sh[j][d];
        g_h[b * NN * EMB + p] = acc;
    }
}

// ---------------- 6. get_seq + hs ---------------------------------------------
__global__ void k_seq(const int* __restrict__ rev, const int* __restrict__ alias,
                      const float* __restrict__ slen) {
    __shared__ float ss[L][EMB];
    int b = blockIdx.x, t = threadIdx.x, nt = blockDim.x;
    for (int p = t; p < L * EMB; p += nt) {
        int l = p / EMB, d = p % EMB;
        int r  = rev[b * L + l];
        int al = alias[b * L + l];
        float v = 0.2f * g_e1t[r * EMB + d] + 0.8f * g_h[(b * NN + al) * EMB + d];
        ss[l][d] = v;
        g_seq[b * L * EMB + p] = v;
    }
    __syncthreads();
    float sl = slen[b];
    for (int d = t; d < EMB; d += nt) {
        float a = 0.f;
        #pragma unroll 5
        for (int l = 0; l < L; l++) a += ss[l][d];
        g_hs[b * EMB + d] = a / sl;
    }
}

// ---------------- 7. soft attention -> sel ------------------------------------
__global__ void k_attn(const float* __restrict__ w1W,
                       const float* __restrict__ g1W, const float* __restrict__ g1b,
                       const float* __restrict__ g2W, const float* __restrict__ w2,
                       const int* __restrict__ mask) {
    __shared__ float ss [L][EMB + 1];
    __shared__ float snh[L][EMB + 1];
    __shared__ float sgh[EMB];
    __shared__ float shsv[EMB];
    __shared__ float sbeta[L];
    int b = blockIdx.x, t = threadIdx.x, nt = blockDim.x;
    int w = t >> 5, lane = t & 31, nw = nt >> 5;
    for (int p = t; p < L * EMB; p += nt) ss[p / EMB][p % EMB] = g_seq[b * L * EMB + p];
    for (int d = t; d < EMB; d += nt) shsv[d] = g_hs[b * EMB + d];
    for (int l = t; l < L; l += nt) sbeta[l] = 0.f;
    __syncthreads();
    for (int o = w; o < EMB; o += nw) {
        float acc = 0.f;
        for (int d = lane; d < EMB; d += 32) acc += shsv[d] * g2W[o * EMB + d];
        acc = wredsum(acc);
        if (lane == 0) sgh[o] = acc;
    }
    for (int p = t; p < L * EMB; p += nt) {
        int o = p / L, l = p % L;
        const float* wr = w1W + o * 2 * EMB + EMB;
        float acc = g_posw[l * EMB + o];
        #pragma unroll 4
        for (int k = 0; k < EMB; k++) acc += ss[l][k] * wr[k];
        snh[l][o] = tanhf(acc);
    }
    __syncthreads();
    for (int p = t; p < L * EMB; p += nt) {
        int o = p / L, l = p % L;
        float acc = g1b[o] + sgh[o];
        const float* wr = g1W + o * EMB;
        #pragma unroll 4
        for (int k = 0; k < EMB; k++) acc += snh[l][k] * wr[k];
        float s = 1.f / (1.f + expf(-acc));
        atomicAdd(&sbeta[l], s * w2[o]);
    }
    __syncthreads();
    for (int l = t; l < L; l += nt) sbeta[l] *= (float)mask[b * L + l];
    __syncthreads();
    for (int d = t; d < EMB; d += nt) {
        float acc = 0.f;
        #pragma unroll 5
        for (int l = 0; l < L; l++) acc += sbeta[l] * ss[l][d];
        g_sel[b * EMB + d] = acc;
    }
}

// ---------------- 8. session conv (hardwired globals) -------------------------
__global__ void k_sessmm1(const float* __restrict__ A) {
    __shared__ float sadj[B];
    int b = blockIdx.x, t = threadIdx.x, nt = blockDim.x;
    for (int j = t; j < B; j += nt) sadj[j] = A[b * B + j];
    __syncthreads();
    for (int d = t; d < EMB; d += nt) {
        float acc = 0.f;
        #pragma unroll 4
        for (int j = 0; j < B; j++) acc += sadj[j] * g_sel[j * EMB + d];
        g_s1[b * EMB + d] = acc;
    }
}
__global__ void k_sessmm2(const float* __restrict__ A) {
    __shared__ float sadj[B];
    int b = blockIdx.x, t = threadIdx.x, nt = blockDim.x;
    for (int j = t; j < B; j += nt) sadj[j] = A[b * B + j];
    __syncthreads();
    for (int d = t; d < EMB; d += nt) {
        float acc = 0.f;
        #pragma unroll 4
        for (int j = 0; j < B; j++) acc += sadj[j] * g_s1[j * EMB + d];
        g_s2[b * EMB + d] = acc;
    }
}

__global__ void k_combine_sess(const float* __restrict__ aw) {
    int wid  = (blockIdx.x * blockDim.x + threadIdx.x) >> 5;
    int lane = threadIdx.x & 31;
    if (wid >= B) return;
    float4 a = {0.f,0.f,0.f,0.f}, bb = a, cc = a;
    if (lane < CH) {
        a  = ((const float4*)g_sel)[wid * CH + lane];
        bb = ((const float4*)g_s1 )[wid * CH + lane];
        cc = ((const float4*)g_s2 )[wid * CH + lane];
    }
    float s0 = a.x*a.x + a.y*a.y + a.z*a.z + a.w*a.w;
    float s1 = bb.x*bb.x + bb.y*bb.y + bb.z*bb.z + bb.w*bb.w;
    float s2 = cc.x*cc.x + cc.y*cc.y + cc.z*cc.z + cc.w*cc.w;
    s0 = wredsum(s0); s1 = wredsum(s1); s2 = wredsum(s2);
    float i0 = aw[0] / fmaxf(sqrtf(s0), 1e-12f);
    float i1 = aw[1] / fmaxf(sqrtf(s1), 1e-12f);
    float i2 = aw[2] / fmaxf(sqrtf(s2), 1e-12f);
    if (lane < CH) {
        float4 r;
        r.x = a.x*i0 + bb.x*i1 + cc.x*i2;
        r.y = a.y*i0 + bb.y*i1 + cc.y*i2;
        r.z = a.z*i0 + bb.z*i1 + cc.z*i2;
        r.w = a.w*i0 + bb.w*i1 + cc.w*i2;
        ((float4*)g_self)[wid * CH + lane] = r;
    }
}

// ---------------- 9. scores = 4 * self @ emb_gnn.T (packed f32x2 FMA) --------
#define SBT 32
#define SNT 64
__global__ void k_scores(float* __restrict__ sc) {
    __shared__ float  sA[SBT][EMB + 4];       // pad 104 floats (16B-aligned rows)
    __shared__ float2 sB2[EMB][SNT / 2];      // [k][pair]: cols (2p, 2p+1)
    int bn = blockIdx.x * SNT;
    int bb = blockIdx.y * SBT;
    int t = threadIdx.x;
    for (int p = t; p < SBT * EMB; p += 256) {
        int r = p / EMB, c = p % EMB;
        sA[r][c] = 4.f * g_self[(bb + r) * EMB + c];
    }
    for (int p = t; p < SNT * EMB; p += 256) {
        int r = p / EMB, c = p % EMB;     // r = local n
        float v = g_e1t[(bn + r + 1) * EMB + c];
        if (r & 1) sB2[c][r >> 1].y = v; else sB2[c][r >> 1].x = v;
    }
    __syncthreads();
    int tx = t & 15, ty = t >> 4;
    unsigned long long acc00 = 0ull, acc01 = 0ull, acc10 = 0ull, acc11 = 0ull;
    #pragma unroll 4
    for (int k = 0; k < EMB; k++) {
        float a0 = sA[ty][k], a1 = sA[ty + 16][k];
        unsigned long long a0d, a1d;
        asm("mov.b64 %0, {%1, %1};" : "=l"(a0d) : "r"(__float_as_uint(a0)));
        asm("mov.b64 %0, {%1, %1};" : "=l"(a1d) : "r"(__float_as_uint(a1)));
        unsigned long long b0 = *reinterpret_cast<const unsigned long long*>(&sB2[k][tx]);
        unsigned long long b1 = *reinterpret_cast<const unsigned long long*>(&sB2[k][tx + 16]);
        asm("fma.rn.f32x2 %0, %1, %2, %0;" : "+l"(acc00) : "l"(a0d), "l"(b0));
        asm("fma.rn.f32x2 %0, %1, %2, %0;" : "+l"(acc01) : "l"(a0d), "l"(b1));
        asm("fma.rn.f32x2 %0, %1, %2, %0;" : "+l"(acc10) : "l"(a1d), "l"(b0));
        asm("fma.rn.f32x2 %0, %1, %2, %0;" : "+l"(acc11) : "l"(a1d), "l"(b1));
    }
    // store as float2 (sc rows are 8B-aligned: output offset is 2 floats)
    size_t r0 = (size_t)(bb + ty) * N_NODE + bn;
    size_t r1 = (size_t)(bb + ty + 16) * N_NODE + bn;
    *reinterpret_cast<float2*>(sc + r0 + 2 * tx)      = *reinterpret_cast<float2*>(&acc00);
    *reinterpret_cast<float2*>(sc + r0 + 2 * tx + 32) = *reinterpret_cast<float2*>(&acc01);
    *reinterpret_cast<float2*>(sc + r1 + 2 * tx)      = *reinterpret_cast<float2*>(&acc10);
    *reinterpret_cast<float2*>(sc + r1 + 2 * tx + 32) = *reinterpret_cast<float2*>(&acc11);
}

// ---------------- 10. per-row LSE: single-pass online, float2 reads -----------
__global__ void k_lse(const float* __restrict__ sc) {
    int b = blockIdx.x, t = threadIdx.x, nt = blockDim.x;
    const float2* row = reinterpret_cast<const float2*>(sc + (size_t)b * N_NODE);
    float m = -INFINITY, s = 0.f;
    for (int i = t; i < N_NODE / 2; i += nt) {
        float2 v = row[i];
        float mv = fmaxf(v.x, v.y);
        if (mv > m) { s *= expf(m - mv); m = mv; }
        s += expf(v.x - m) + expf(v.y - m);
    }
    #pragma unroll
    for (int o = 16; o; o >>= 1) {
        float mo = __shfl_xor_sync(FULLM, m, o);
        float so = __shfl_xor_sync(FULLM, s, o);
        float mn = fmaxf(m, mo);
        s = s * expf(m - mn) + so * expf(mo - mn);
        m = mn;
    }
    __shared__ float sm[8], sv[8];
    if ((t & 31) == 0) { sm[t >> 5] = m; sv[t >> 5] = s; }
    __syncthreads();
    if (t == 0) {
        float M = sm[0], S = sv[0];
        for (int w = 1; w < nt / 32; w++) {
            float mn = fmaxf(M, sm[w]);
            S = S * expf(M - mn) + sv[w] * expf(sm[w] - mn);
            M = mn;
        }
        g_lse[b] = M + logf(S);
    }
}

// ---------------- 11. loss -----------------------------------------------------
__global__ void k_loss(const float* __restrict__ sc, const int* __restrict__ tar,
                       float* __restrict__ out, int off) {
    int t = threadIdx.x;  // 512 threads == B
    float v = sc[(size_t)t * N_NODE + tar[t]] - g_lse[t];
    v = wredsum(v);
    __shared__ float sp[16];
    if ((t & 31) == 0) sp[t >> 5] = v;
    __syncthreads();
    if (t == 0) {
        float tot = 0.f;
        for (int w = 0; w < 16; w++) tot += sp[w];
        float loss = -tot / (float)B;
        if (off >= 2)      { out[0] = 0.f; out[1] = loss; }
        else if (off == 1) { out[0] = loss; }
    }
}

// ---------------- host launcher ------------------------------------------------
extern "C" void kernel_launch(void* const* d_in, const int* in_sizes, int n_in,
                              void* d_out, int out_size) {
    int sh = (n_in >= 6 && in_sizes[5] == 1) ? 0 : -1;

    const int*   tar   = (const int*  )d_in[0];
    const int*   rev   = (const int*  )d_in[1];
    const int*   mask  = (const int*  )d_in[2];
    const float* slen  = (const float*)d_in[3];
    const float* sadj  = (const float*)d_in[4];
    const int*   items = (const int*  )d_in[6 + sh];
    const int*   adj   = (const int*  )d_in[7 + sh];
    const int*   alias = (const int*  )d_in[8 + sh];
    const int*   rows  = (const int*  )d_in[9 + sh];
    const int*   cols  = (const int*  )d_in[10 + sh];
    const float* vals  = (const float*)d_in[11 + sh];
    const float* nemb  = (const float*)d_in[12 + sh];
    const float* bit   = (const float*)d_in[13 + sh];
    const float* asess = (const float*)d_in[14 + sh];
    const float* a0    = (const float*)d_in[15 + sh];
    const float* a1    = (const float*)d_in[16 + sh];
    const float* a2    = (const float*)d_in[17 + sh];
    const float* a3    = (const float*)d_in[18 + sh];
    const float* w1W   = (const float*)d_in[19 + sh];
    const float* w1b   = (const float*)d_in[20 + sh];
    const float* w2    = (const float*)d_in[21 + sh];
    const float* g1W   = (const float*)d_in[22 + sh];
    const float* g1b   = (const float*)d_in[23 + sh];
    const float* g2W   = (const float*)d_in[24 + sh];
    const float* pos   = (const float*)d_in[25 + sh];

    float* outf = (float*)d_out;
    int off = out_size - B * N_NODE;
    if (off < 0) off = 0;
    float* scores = outf + off;

    k_zero<<<(N_NODE + 255) / 256, 256>>>();
    k_hist<<<(E_EDGES + 255) / 256, 256>>>(rows);
    k_scan<<<1, NT_SCAN>>>();
    k_scatter<<<(E_EDGES + 255) / 256, 256>>>(rows, cols, vals);
    k_spmm_csr1<<<(N_NODE * 32 + 255) / 256, 256>>>(nemb);
    k_spmm_csr2<<<(N_NODE * 32 + 255) / 256, 256>>>();
    k_combine_item<<<(N_NODE * 32 + 255) / 256, 256>>>(nemb, bit);
    k_posw<<<(L * EMB * 32 + 255) / 256, 256>>>(pos, w1W, w1b);
    k_gat<<<B, 256>>>(items, adj, a0, a1, a2, a3);
    k_seq<<<B, 128>>>(rev, alias, slen);
    k_attn<<<B, 256>>>(w1W, g1W, g1b, g2W, w2, mask);
    k_sessmm1<<<B, 128>>>(sadj);
    k_sessmm2<<<B, 128>>>(sadj);
    k_combine_sess<<<(B * 32 + 255) / 256, 256>>>(asess);
    k_scores<<<dim3(N_NODE / SNT, B / SBT), 256>>>(scores);
    k_lse<<<B, 256>>>(scores);
    k_loss<<<1, 512>>>(scores, tar, outf, off);
}

// round 15
// speedup vs baseline: 1.2421x; 1.2421x over previous
#include <cuda_runtime.h>
#include <math.h>
#include <stddef.h>

#define N_NODE 40000
#define EMB    100
#define CH     25        // float4 chunks per embedding row
#define B      512
#define L      50
#define NN     50
#define E_EDGES 800000
#define FULLM  0xffffffffu

// ---- scratch: device globals, referenced ONLY from device code -------------
// (BSS zero-init is guaranteed; g_e1t row 0 is never written -> stays zero.)
__device__ __align__(16) float g_x1[N_NODE * EMB];
__device__ __align__(16) float g_x2[N_NODE * EMB];
__device__ __align__(16) float g_e1t[(N_NODE + 1) * EMB];
__device__ __align__(16) float g_h[B * NN * EMB];
__device__ __align__(16) float g_seq[B * L * EMB];
__device__ __align__(16) float g_hs[B * EMB];
__device__ __align__(16) float g_posw[L * EMB];
__device__ __align__(16) float g_sel[B * EMB];
__device__ __align__(16) float g_s1[B * EMB];
__device__ __align__(16) float g_self[B * EMB];
__device__ float g_lse[B];

// CSR scratch (g_cnt re-zeroed at end of each replay by k_lse)
__device__ int   g_cnt[N_NODE];
__device__ int   g_off[N_NODE + 1];
__device__ int   g_pos[N_NODE];
__device__ int   g_ecol[E_EDGES];
__device__ float g_eval[E_EDGES];

__device__ __forceinline__ float wredsum(float v) {
    #pragma unroll
    for (int o = 16; o; o >>= 1) v += __shfl_xor_sync(FULLM, v, o);
    return v;
}
__device__ __forceinline__ float wredmax(float v) {
    #pragma unroll
    for (int o = 16; o; o >>= 1) v = fmaxf(v, __shfl_xor_sync(FULLM, v, o));
    return v;
}

// ---------------- 1a. histogram of row ids (g_cnt pre-zeroed) ----------------
__global__ void k_hist(const int* __restrict__ rows) {
    int e = blockIdx.x * blockDim.x + threadIdx.x;
    if (e < E_EDGES) atomicAdd(&g_cnt[rows[e]], 1);
}

// ---------------- 1b. exclusive scan (single block) ---------------------------
#define NT_SCAN 1024
#define SCHUNK ((N_NODE + NT_SCAN - 1) / NT_SCAN)   // 40
__global__ void k_scan() {
    __shared__ int ps[NT_SCAN];
    int t = threadIdx.x;
    int base = t * SCHUNK;
    int s = 0;
    for (int i = 0; i < SCHUNK; i++) {
        int idx = base + i;
        if (idx < N_NODE) s += g_cnt[idx];
    }
    ps[t] = s;
    __syncthreads();
    for (int o = 1; o < NT_SCAN; o <<= 1) {
        int v = (t >= o) ? ps[t - o] : 0;
        __syncthreads();
        ps[t] += v;
        __syncthreads();
    }
    int run = (t > 0) ? ps[t - 1] : 0;
    for (int i = 0; i < SCHUNK; i++) {
        int idx = base + i;
        if (idx < N_NODE) {
            int c = g_cnt[idx];
            g_off[idx] = run;
            g_pos[idx] = run;
            run += c;
        }
    }
    if (t == NT_SCAN - 1) g_off[N_NODE] = run;
}

// ---------------- 1c. scatter edges into row-sorted order ---------------------
__global__ void k_scatter(const int* __restrict__ rows, const int* __restrict__ cols,
                          const float* __restrict__ vals) {
    int e = blockIdx.x * blockDim.x + threadIdx.x;
    if (e >= E_EDGES) return;
    int p = atomicAdd(&g_pos[rows[e]], 1);
    g_ecol[p] = cols[e];
    g_eval[p] = vals[e];
}

// ---------------- 2. SpMM: warp/row, unroll x4 (MLP=4), no shuffles ----------
__device__ __forceinline__ void spmm_row4(const float* __restrict__ in,
                                          float* __restrict__ out,
                                          int row, int lane) {
    int s = g_off[row], e = g_off[row + 1];
    float4 acc = {0.f, 0.f, 0.f, 0.f};
    int i = s;
    for (; i + 4 <= e; i += 4) {
        int   c0 = g_ecol[i],     c1 = g_ecol[i + 1];
        int   c2 = g_ecol[i + 2], c3 = g_ecol[i + 3];
        float v0 = g_eval[i],     v1 = g_eval[i + 1];
        float v2 = g_eval[i + 2], v3 = g_eval[i + 3];
        if (lane < CH) {
            float4 x0 = ((const float4*)in)[c0 * CH + lane];
            float4 x1 = ((const float4*)in)[c1 * CH + lane];
            float4 x2 = ((const float4*)in)[c2 * CH + lane];
            float4 x3 = ((const float4*)in)[c3 * CH + lane];
            acc.x += v0 * x0.x; acc.y += v0 * x0.y; acc.z += v0 * x0.z; acc.w += v0 * x0.w;
            acc.x += v1 * x1.x; acc.y += v1 * x1.y; acc.z += v1 * x1.z; acc.w += v1 * x1.w;
            acc.x += v2 * x2.x; acc.y += v2 * x2.y; acc.z += v2 * x2.z; acc.w += v2 * x2.w;
            acc.x += v3 * x3.x; acc.y += v3 * x3.y; acc.z += v3 * x3.z; acc.w += v3 * x3.w;
        }
    }
    for (; i < e; i++) {
        int   c = g_ecol[i];
        float v = g_eval[i];
        if (lane < CH) {
            float4 x = ((const float4*)in)[c * CH + lane];
            acc.x += v * x.x; acc.y += v * x.y; acc.z += v * x.z; acc.w += v * x.w;
        }
    }
    if (lane < CH) ((float4*)out)[row * CH + lane] = acc;
}
__global__ void k_spmm_csr1(const float* __restrict__ in) {
    int wid  = (blockIdx.x * blockDim.x + threadIdx.x) >> 5;
    int lane = threadIdx.x & 31;
    if (wid < N_NODE) spmm_row4(in, g_x1, wid, lane);
}
__global__ void k_spmm_csr2() {
    int wid  = (blockIdx.x * blockDim.x + threadIdx.x) >> 5;
    int lane = threadIdx.x & 31;
    if (wid < N_NODE) spmm_row4(g_x1, g_x2, wid, lane);
}

// ---------------- 3. per-node l2norm + weighted sum -> e1t[1..] --------------
__global__ void k_combine_item(const float* __restrict__ emb, const float* __restrict__ bw) {
    int wid  = (blockIdx.x * blockDim.x + threadIdx.x) >> 5;
    int lane = threadIdx.x & 31;
    if (wid >= N_NODE) return;
    float4 a = {0.f,0.f,0.f,0.f}, bb = a, cc = a;
    if (lane < CH) {
        a  = ((const float4*)emb )[wid * CH + lane];
        bb = ((const float4*)g_x1)[wid * CH + lane];
        cc = ((const float4*)g_x2)[wid * CH + lane];
    }
    float s0 = a.x*a.x + a.y*a.y + a.z*a.z + a.w*a.w;
    float s1 = bb.x*bb.x + bb.y*bb.y + bb.z*bb.z + bb.w*bb.w;
    float s2 = cc.x*cc.x + cc.y*cc.y + cc.z*cc.z + cc.w*cc.w;
    s0 = wredsum(s0); s1 = wredsum(s1); s2 = wredsum(s2);
    float i0 = bw[0] / fmaxf(sqrtf(s0), 1e-12f);
    float i1 = bw[1] / fmaxf(sqrtf(s1), 1e-12f);
    float i2 = bw[2] / fmaxf(sqrtf(s2), 1e-12f);
    if (lane < CH) {
        float4 r;
        r.x = a.x*i0 + bb.x*i1 + cc.x*i2;
        r.y = a.y*i0 + bb.y*i1 + cc.y*i2;
        r.z = a.z*i0 + bb.z*i1 + cc.z*i2;
        r.w = a.w*i0 + bb.w*i1 + cc.w*i2;
        ((float4*)g_e1t)[(wid + 1) * CH + lane] = r;
    }
}

// ---------------- 4. posw[l][o] = pos[l] . w1W[o, :100] + w1b[o] -------------
__global__ void k_posw(const float* __restrict__ pos, const float* __restrict__ w1W,
                       const float* __restrict__ w1b) {
    int gw   = (blockIdx.x * blockDim.x + threadIdx.x) >> 5;
    int lane = threadIdx.x & 31;
    if (gw >= L * EMB) return;
    int l = gw / EMB, o = gw % EMB;
    const float* wr = w1W + o * 2 * EMB;
    float acc = 0.f;
    for (int k = lane; k < EMB; k += 32) acc += pos[l * EMB + k] * wr[k];
    acc = wredsum(acc);
    if (lane == 0) g_posw[l * EMB + o] = acc + w1b[o];
}

// ---------------- 5. GAT per batch element (padded shared) -------------------
__global__ void k_gat(const int* __restrict__ items, const int* __restrict__ adj,
                      const float* __restrict__ a0, const float* __restrict__ a1,
                      const float* __restrict__ a2, const float* __restrict__ a3) {
    __shared__ float sh[NN][EMB + 1];
    __shared__ float sa[4][EMB + 1];
    __shared__ float se[NN][NN];
    __shared__ int   sit[NN];
    int b = blockIdx.x, t = threadIdx.x, nt = blockDim.x;
    for (int i = t; i < NN; i += nt) sit[i] = items[b * NN + i];
    for (int i = t; i < EMB; i += nt) {
        sa[0][i] = a0[i]; sa[1][i] = a1[i]; sa[2][i] = a2[i]; sa[3][i] = a3[i];
    }
    __syncthreads();
    for (int p = t; p < NN * EMB; p += nt)
        sh[p / EMB][p % EMB] = g_e1t[sit[p / EMB] * EMB + p % EMB];
    __syncthreads();
    for (int p = t; p < NN * NN; p += nt) {
        int i = p / NN, j = p % NN;
        int av = adj[b * NN * NN + p];
        float ev;
        if (av >= 1 && av <= 4) {
            const float* ak = sa[av - 1];
            float acc = 0.f;
            #pragma unroll 4
            for (int d = 0; d < EMB; d++) acc += sh[i][d] * ak[d] * sh[j][d];
            ev = acc > 0.f ? acc : 0.2f * acc;
        } else ev = -9e15f;
        se[i][j] = ev;
    }
    __syncthreads();
    int w = t >> 5, lane = t & 31, nw = nt >> 5;
    for (int i = w; i < NN; i += nw) {
        float m = -INFINITY;
        for (int j = lane; j < NN; j += 32) m = fmaxf(m, se[i][j]);
        m = wredmax(m);
        float s = 0.f;
        for (int j = lane; j < NN; j += 32) { float ex = expf(se[i][j] - m); se[i][j] = ex; s += ex; }
        s = wredsum(s);
        float inv = 1.f / s;
        for (int j = lane; j < NN; j += 32) se[i][j] *= inv;
    }
    __syncthreads();
    for (int p = t; p < NN * EMB; p += nt) {
        int i = p / EMB, d = p % EMB;
        float acc = 0.f;
        #pragma unroll 5
        for (int j = 0; j < NN; j++) acc += se[i][j] * sh[j][d];
        g_h[b * NN * EMB + p] = acc;
    }
}

// ---------------- 6. get_seq + hs ---------------------------------------------
__global__ void k_seq(const int* __restrict__ rev, const int* __restrict__ alias,
                      const float* __restrict__ slen) {
    __shared__ float ss[L][EMB];
    int b = blockIdx.x, t = threadIdx.x, nt = blockDim.x;
    for (int p = t; p < L * EMB; p += nt) {
        int l = p / EMB, d = p % EMB;
        int r  = rev[b * L + l];
        int al = alias[b * L + l];
        float v = 0.2f * g_e1t[r * EMB + d] + 0.8f * g_h[(b * NN + al) * EMB + d];
        ss[l][d] = v;
        g_seq[b * L * EMB + p] = v;
    }
    __syncthreads();
    float sl = slen[b];
    for (int d = t; d < EMB; d += nt) {
        float a = 0.f;
        #pragma unroll 5
        for (int l = 0; l < L; l++) a += ss[l][d];
        g_hs[b * EMB + d] = a / sl;
    }
}

// ---------------- 7. soft attention -> sel ------------------------------------
__global__ void k_attn(const float* __restrict__ w1W,
                       const float* __restrict__ g1W, const float* __restrict__ g1b,
                       const float* __restrict__ g2W, const float* __restrict__ w2,
                       const int* __restrict__ mask) {
    __shared__ float ss [L][EMB + 1];
    __shared__ float snh[L][EMB + 1];
    __shared__ float sgh[EMB];
    __shared__ float shsv[EMB];
    __shared__ float sbeta[L];
    int b = blockIdx.x, t = threadIdx.x, nt = blockDim.x;
    int w = t >> 5, lane = t & 31, nw = nt >> 5;
    for (int p = t; p < L * EMB; p += nt) ss[p / EMB][p % EMB] = g_seq[b * L * EMB + p];
    for (int d = t; d < EMB; d += nt) shsv[d] = g_hs[b * EMB + d];
    for (int l = t; l < L; l += nt) sbeta[l] = 0.f;
    __syncthreads();
    for (int o = w; o < EMB; o += nw) {
        float acc = 0.f;
        for (int d = lane; d < EMB; d += 32) acc += shsv[d] * g2W[o * EMB + d];
        acc = wredsum(acc);
        if (lane == 0) sgh[o] = acc;
    }
    for (int p = t; p < L * EMB; p += nt) {
        int o = p / L, l = p % L;
        const float* wr = w1W + o * 2 * EMB + EMB;
        float acc = g_posw[l * EMB + o];
        #pragma unroll 4
        for (int k = 0; k < EMB; k++) acc += ss[l][k] * wr[k];
        snh[l][o] = tanhf(acc);
    }
    __syncthreads();
    for (int p = t; p < L * EMB; p += nt) {
        int o = p / L, l = p % L;
        float acc = g1b[o] + sgh[o];
        const float* wr = g1W + o * EMB;
        #pragma unroll 4
        for (int k = 0; k < EMB; k++) acc += snh[l][k] * wr[k];
        float s = 1.f / (1.f + expf(-acc));
        atomicAdd(&sbeta[l], s * w2[o]);
    }
    __syncthreads();
    for (int l = t; l < L; l += nt) sbeta[l] *= (float)mask[b * L + l];
    __syncthreads();
    for (int d = t; d < EMB; d += nt) {
        float acc = 0.f;
        #pragma unroll 5
        for (int l = 0; l < L; l++) acc += sbeta[l] * ss[l][d];
        g_sel[b * EMB + d] = acc;
    }
}

// ---------------- 8a. session conv 1: g_s1 = A @ g_sel -------------------------
__global__ void k_sessmm1(const float* __restrict__ A) {
    __shared__ float sadj[B];
    int b = blockIdx.x, t = threadIdx.x, nt = blockDim.x;
    for (int j = t; j < B; j += nt) sadj[j] = A[b * B + j];
    __syncthreads();
    for (int d = t; d < EMB; d += nt) {
        float acc = 0.f;
        #pragma unroll 4
        for (int j = 0; j < B; j++) acc += sadj[j] * g_sel[j * EMB + d];
        g_s1[b * EMB + d] = acc;
    }
}

// ---------------- 8b. session conv 2 fused with l2norm combine -> g_self ------
__global__ void k_sessmm2c(const float* __restrict__ A, const float* __restrict__ aw) {
    __shared__ float sadj[B];
    __shared__ float red0[128], red1[128], red2[128];
    int b = blockIdx.x, t = threadIdx.x;          // 128 threads
    for (int j = t; j < B; j += 128) sadj[j] = A[b * B + j];
    __syncthreads();
    float s2v = 0.f, selv = 0.f, s1v = 0.f;
    if (t < EMB) {
        float acc = 0.f;
        #pragma unroll 4
        for (int j = 0; j < B; j++) acc += sadj[j] * g_s1[j * EMB + t];
        s2v  = acc;
        selv = g_sel[b * EMB + t];
        s1v  = g_s1[b * EMB + t];
    }
    red0[t] = selv * selv; red1[t] = s1v * s1v; red2[t] = s2v * s2v;
    __syncthreads();
    for (int o = 64; o; o >>= 1) {
        if (t < o) { red0[t] += red0[t + o]; red1[t] += red1[t + o]; red2[t] += red2[t + o]; }
        __syncthreads();
    }
    float i0 = aw[0] / fmaxf(sqrtf(red0[0]), 1e-12f);
    float i1 = aw[1] / fmaxf(sqrtf(red1[0]), 1e-12f);
    float i2 = aw[2] / fmaxf(sqrtf(red2[0]), 1e-12f);
    if (t < EMB) g_self[b * EMB + t] = selv * i0 + s1v * i1 + s2v * i2;
}

// ---------------- 9. scores = 4 * self @ emb_gnn.T (f32x2, conflict-free) -----
#define SBT 32
#define SNT 64
__global__ void k_scores(float* __restrict__ sc) {
    __shared__ float2 sA2[SBT][EMB + 1];    // {a,a}: row 808B, 8B-aligned
    __shared__ float  sB[EMB][SNT + 2];     // row 264B: fill/read conflict-light
    int bn = blockIdx.x * SNT;
    int bb = blockIdx.y * SBT;
    int t = threadIdx.x;
    for (int p = t; p < SBT * EMB; p += 256) {
        int r = p / EMB, c = p % EMB;
        float v = 4.f * g_self[(bb + r) * EMB + c];
        sA2[r][c] = make_float2(v, v);
    }
    for (int p = t; p < SNT * EMB; p += 256) {
        int r = p / EMB, c = p % EMB;       // coalesced global read over c
        sB[c][r] = g_e1t[(bn + r + 1) * EMB + c];
    }
    __syncthreads();
    int tx = t & 15, ty = t >> 4;
    unsigned long long acc00 = 0ull, acc01 = 0ull, acc10 = 0ull, acc11 = 0ull;
    #pragma unroll 4
    for (int k = 0; k < EMB; k++) {
        unsigned long long a0d = *reinterpret_cast<const unsigned long long*>(&sA2[ty][k]);
        unsigned long long a1d = *reinterpret_cast<const unsigned long long*>(&sA2[ty + 16][k]);
        unsigned long long b0  = *reinterpret_cast<const unsigned long long*>(&sB[k][2 * tx]);
        unsigned long long b1  = *reinterpret_cast<const unsigned long long*>(&sB[k][2 * tx + 32]);
        asm("fma.rn.f32x2 %0, %1, %2, %0;" : "+l"(acc00) : "l"(a0d), "l"(b0));
        asm("fma.rn.f32x2 %0, %1, %2, %0;" : "+l"(acc01) : "l"(a0d), "l"(b1));
        asm("fma.rn.f32x2 %0, %1, %2, %0;" : "+l"(acc10) : "l"(a1d), "l"(b0));
        asm("fma.rn.f32x2 %0, %1, %2, %0;" : "+l"(acc11) : "l"(a1d), "l"(b1));
    }
    size_t r0 = (size_t)(bb + ty) * N_NODE + bn;
    size_t r1 = (size_t)(bb + ty + 16) * N_NODE + bn;
    *reinterpret_cast<float2*>(sc + r0 + 2 * tx)      = *reinterpret_cast<float2*>(&acc00);
    *reinterpret_cast<float2*>(sc + r0 + 2 * tx + 32) = *reinterpret_cast<float2*>(&acc01);
    *reinterpret_cast<float2*>(sc + r1 + 2 * tx)      = *reinterpret_cast<float2*>(&acc10);
    *reinterpret_cast<float2*>(sc + r1 + 2 * tx + 32) = *reinterpret_cast<float2*>(&acc11);
}

// ---------------- 10. per-row LSE (online) + re-zero g_cnt for next replay ----
__global__ void k_lse(const float* __restrict__ sc) {
    int b = blockIdx.x, t = threadIdx.x, nt = blockDim.x;
    const float2* row = reinterpret_cast<const float2*>(sc + (size_t)b * N_NODE);
    float m = -INFINITY, s = 0.f;
    for (int i = t; i < N_NODE / 2; i += nt) {
        float2 v = row[i];
        float mv = fmaxf(v.x, v.y);
        if (mv > m) { s *= expf(m - mv); m = mv; }
        s += expf(v.x - m) + expf(v.y - m);
    }
    #pragma unroll
    for (int o = 16; o; o >>= 1) {
        float mo = __shfl_xor_sync(FULLM, m, o);
        float so = __shfl_xor_sync(FULLM, s, o);
        float mn = fmaxf(m, mo);
        s = s * expf(m - mn) + so * expf(mo - mn);
        m = mn;
    }
    __shared__ float sm[8], sv[8];
    if ((t & 31) == 0) { sm[t >> 5] = m; sv[t >> 5] = s; }
    __syncthreads();
    if (t == 0) {
        float M = sm[0], S = sv[0];
        for (int w = 1; w < nt / 32; w++) {
            float mn = fmaxf(M, sm[w]);
            S = S * expf(M - mn) + sv[w] * expf(sm[w] - mn);
            M = mn;
        }
        g_lse[b] = M + logf(S);
    }
    // fold: reset CSR histogram for next graph replay (deterministic:
    // g_cnt starts BSS-zero; hist of replay N sees zeros written here in N-1)
    int gid = b * nt + t;
    if (gid < N_NODE) g_cnt[gid] = 0;
}

// ---------------- 11. loss -----------------------------------------------------
__global__ void k_loss(const float* __restrict__ sc, const int* __restrict__ tar,
                       float* __restrict__ out, int off) {
    int t = threadIdx.x;  // 512 threads == B
    float v = sc[(size_t)t * N_NODE + tar[t]] - g_lse[t];
    v = wredsum(v);
    __shared__ float sp[16];
    if ((t & 31) == 0) sp[t >> 5] = v;
    __syncthreads();
    if (t == 0) {
        float tot = 0.f;
        for (int w = 0; w < 16; w++) tot += sp[w];
        float loss = -tot / (float)B;
        if (off >= 2)      { out[0] = 0.f; out[1] = loss; }
        else if (off == 1) { out[0] = loss; }
    }
}

// ---------------- host launcher ------------------------------------------------
extern "C" void kernel_launch(void* const* d_in, const int* in_sizes, int n_in,
                              void* d_out, int out_size) {
    int sh = (n_in >= 6 && in_sizes[5] == 1) ? 0 : -1;

    const int*   tar   = (const int*  )d_in[0];
    const int*   rev   = (const int*  )d_in[1];
    const int*   mask  = (const int*  )d_in[2];
    const float* slen  = (const float*)d_in[3];
    const float* sadj  = (const float*)d_in[4];
    const int*   items = (const int*  )d_in[6 + sh];
    const int*   adj   = (const int*  )d_in[7 + sh];
    const int*   alias = (const int*  )d_in[8 + sh];
    const int*   rows  = (const int*  )d_in[9 + sh];
    const int*   cols  = (const int*  )d_in[10 + sh];
    const float* vals  = (const float*)d_in[11 + sh];
    const float* nemb  = (const float*)d_in[12 + sh];
    const float* bit   = (const float*)d_in[13 + sh];
    const float* asess = (const float*)d_in[14 + sh];
    const float* a0    = (const float*)d_in[15 + sh];
    const float* a1    = (const float*)d_in[16 + sh];
    const float* a2    = (const float*)d_in[17 + sh];
    const float* a3    = (const float*)d_in[18 + sh];
    const float* w1W   = (const float*)d_in[19 + sh];
    const float* w1b   = (const float*)d_in[20 + sh];
    const float* w2    = (const float*)d_in[21 + sh];
    const float* g1W   = (const float*)d_in[22 + sh];
    const float* g1b   = (const float*)d_in[23 + sh];
    const float* g2W   = (const float*)d_in[24 + sh];
    const float* pos   = (const float*)d_in[25 + sh];

    float* outf = (float*)d_out;
    int off = out_size - B * N_NODE;
    if (off < 0) off = 0;
    float* scores = outf + off;

    // launch #4 is k_spmm_csr1 -> that's the one ncu captures
    k_hist<<<(E_EDGES + 255) / 256, 256>>>(rows);
    k_scan<<<1, NT_SCAN>>>();
    k_scatter<<<(E_EDGES + 255) / 256, 256>>>(rows, cols, vals);
    k_spmm_csr1<<<(N_NODE * 32 + 255) / 256, 256>>>(nemb);
    k_spmm_csr2<<<(N_NODE * 32 + 255) / 256, 256>>>();
    k_combine_item<<<(N_NODE * 32 + 255) / 256, 256>>>(nemb, bit);
    k_posw<<<(L * EMB * 32 + 255) / 256, 256>>>(pos, w1W, w1b);
    k_gat<<<B, 256>>>(items, adj, a0, a1, a2, a3);
    k_seq<<<B, 128>>>(rev, alias, slen);
    k_attn<<<B, 256>>>(w1W, g1W, g1b, g2W, w2, mask);
    k_sessmm1<<<B, 128>>>(sadj);
    k_sessmm2c<<<B, 128>>>(sadj, asess);
    k_scores<<<dim3(N_NODE / SNT, B / SBT), 256>>>(scores);
    k_lse<<<B, 256>>>(scores);
    k_loss<<<1, 512>>>(scores, tar, outf, off);
}

// round 16
// speedup vs baseline: 1.3369x; 1.0763x over previous
#include <cuda_runtime.h>
#include <math.h>
#include <stddef.h>

#define N_NODE 40000
#define EMB    100
#define CH     25        // float4 chunks per embedding row
#define B      512
#define L      50
#define NN     50
#define E_EDGES 800000
#define FULLM  0xffffffffu

// ---- scratch: device globals, referenced ONLY from device code -------------
__device__ __align__(16) float g_x1[N_NODE * EMB];
__device__ __align__(16) float g_x2[N_NODE * EMB];
__device__ __align__(16) float g_e1t[(N_NODE + 1) * EMB];
__device__ __align__(16) float g_h[B * NN * EMB];
__device__ __align__(16) float g_seq[B * L * EMB];
__device__ __align__(16) float g_hs[B * EMB];
__device__ __align__(16) float g_posw[L * EMB];
__device__ __align__(16) float g_sel[B * EMB];
__device__ __align__(16) float g_s1[B * EMB];
__device__ __align__(16) float g_self[B * EMB];
__device__ float g_lse[B];

// CSR scratch (g_cnt re-zeroed at end of each replay by k_lse)
__device__ int   g_cnt[N_NODE];
__device__ int   g_off[N_NODE + 1];
__device__ int   g_pos[N_NODE];
__device__ int   g_ecol[E_EDGES];
__device__ float g_eval[E_EDGES];

__device__ __forceinline__ float wredsum(float v) {
    #pragma unroll
    for (int o = 16; o; o >>= 1) v += __shfl_xor_sync(FULLM, v, o);
    return v;
}
__device__ __forceinline__ float wredmax(float v) {
    #pragma unroll
    for (int o = 16; o; o >>= 1) v = fmaxf(v, __shfl_xor_sync(FULLM, v, o));
    return v;
}

// ---------------- 1a. histogram of row ids (g_cnt pre-zeroed) ----------------
__global__ void k_hist(const int* __restrict__ rows) {
    int e = blockIdx.x * blockDim.x + threadIdx.x;
    if (e < E_EDGES) atomicAdd(&g_cnt[rows[e]], 1);
}

// ---------------- 1b. exclusive scan (single block) ---------------------------
#define NT_SCAN 1024
#define SCHUNK ((N_NODE + NT_SCAN - 1) / NT_SCAN)   // 40
__global__ void k_scan() {
    __shared__ int ps[NT_SCAN];
    int t = threadIdx.x;
    int base = t * SCHUNK;
    int s = 0;
    for (int i = 0; i < SCHUNK; i++) {
        int idx = base + i;
        if (idx < N_NODE) s += g_cnt[idx];
    }
    ps[t] = s;
    __syncthreads();
    for (int o = 1; o < NT_SCAN; o <<= 1) {
        int v = (t >= o) ? ps[t - o] : 0;
        __syncthreads();
        ps[t] += v;
        __syncthreads();
    }
    int run = (t > 0) ? ps[t - 1] : 0;
    for (int i = 0; i < SCHUNK; i++) {
        int idx = base + i;
        if (idx < N_NODE) {
            int c = g_cnt[idx];
            g_off[idx] = run;
            g_pos[idx] = run;
            run += c;
        }
    }
    if (t == NT_SCAN - 1) g_off[N_NODE] = run;
}

// ---------------- 1c. scatter edges into row-sorted order ---------------------
__global__ void k_scatter(const int* __restrict__ rows, const int* __restrict__ cols,
                          const float* __restrict__ vals) {
    int e = blockIdx.x * blockDim.x + threadIdx.x;
    if (e >= E_EDGES) return;
    int p = atomicAdd(&g_pos[rows[e]], 1);
    g_ecol[p] = cols[e];
    g_eval[p] = vals[e];
}

// ---------------- 2. SpMM: warp/row, unroll x4 (MLP=4) ------------------------
__device__ __forceinline__ void spmm_row4(const float* __restrict__ in,
                                          float* __restrict__ out,
                                          int row, int lane) {
    int s = g_off[row], e = g_off[row + 1];
    float4 acc = {0.f, 0.f, 0.f, 0.f};
    int i = s;
    for (; i + 4 <= e; i += 4) {
        int   c0 = g_ecol[i],     c1 = g_ecol[i + 1];
        int   c2 = g_ecol[i + 2], c3 = g_ecol[i + 3];
        float v0 = g_eval[i],     v1 = g_eval[i + 1];
        float v2 = g_eval[i + 2], v3 = g_eval[i + 3];
        if (lane < CH) {
            float4 x0 = ((const float4*)in)[c0 * CH + lane];
            float4 x1 = ((const float4*)in)[c1 * CH + lane];
            float4 x2 = ((const float4*)in)[c2 * CH + lane];
            float4 x3 = ((const float4*)in)[c3 * CH + lane];
            acc.x += v0 * x0.x; acc.y += v0 * x0.y; acc.z += v0 * x0.z; acc.w += v0 * x0.w;
            acc.x += v1 * x1.x; acc.y += v1 * x1.y; acc.z += v1 * x1.z; acc.w += v1 * x1.w;
            acc.x += v2 * x2.x; acc.y += v2 * x2.y; acc.z += v2 * x2.z; acc.w += v2 * x2.w;
            acc.x += v3 * x3.x; acc.y += v3 * x3.y; acc.z += v3 * x3.z; acc.w += v3 * x3.w;
        }
    }
    for (; i < e; i++) {
        int   c = g_ecol[i];
        float v = g_eval[i];
        if (lane < CH) {
            float4 x = ((const float4*)in)[c * CH + lane];
            acc.x += v * x.x; acc.y += v * x.y; acc.z += v * x.z; acc.w += v * x.w;
        }
    }
    if (lane < CH) ((float4*)out)[row * CH + lane] = acc;
}
__global__ void k_spmm_csr1(const float* __restrict__ in) {
    int wid  = (blockIdx.x * blockDim.x + threadIdx.x) >> 5;
    int lane = threadIdx.x & 31;
    if (wid < N_NODE) spmm_row4(in, g_x1, wid, lane);
}
__global__ void k_spmm_csr2() {
    int wid  = (blockIdx.x * blockDim.x + threadIdx.x) >> 5;
    int lane = threadIdx.x & 31;
    if (wid < N_NODE) spmm_row4(g_x1, g_x2, wid, lane);
}

// ---------------- 3. per-node l2norm + weighted sum -> e1t[1..] --------------
__global__ void k_combine_item(const float* __restrict__ emb, const float* __restrict__ bw) {
    int wid  = (blockIdx.x * blockDim.x + threadIdx.x) >> 5;
    int lane = threadIdx.x & 31;
    if (wid >= N_NODE) return;
    float4 a = {0.f,0.f,0.f,0.f}, bb = a, cc = a;
    if (lane < CH) {
        a  = ((const float4*)emb )[wid * CH + lane];
        bb = ((const float4*)g_x1)[wid * CH + lane];
        cc = ((const float4*)g_x2)[wid * CH + lane];
    }
    float s0 = a.x*a.x + a.y*a.y + a.z*a.z + a.w*a.w;
    float s1 = bb.x*bb.x + bb.y*bb.y + bb.z*bb.z + bb.w*bb.w;
    float s2 = cc.x*cc.x + cc.y*cc.y + cc.z*cc.z + cc.w*cc.w;
    s0 = wredsum(s0); s1 = wredsum(s1); s2 = wredsum(s2);
    float i0 = bw[0] / fmaxf(sqrtf(s0), 1e-12f);
    float i1 = bw[1] / fmaxf(sqrtf(s1), 1e-12f);
    float i2 = bw[2] / fmaxf(sqrtf(s2), 1e-12f);
    if (lane < CH) {
        float4 r;
        r.x = a.x*i0 + bb.x*i1 + cc.x*i2;
        r.y = a.y*i0 + bb.y*i1 + cc.y*i2;
        r.z = a.z*i0 + bb.z*i1 + cc.z*i2;
        r.w = a.w*i0 + bb.w*i1 + cc.w*i2;
        ((float4*)g_e1t)[(wid + 1) * CH + lane] = r;
    }
}

// ---------------- 4. posw[l][o] = pos[l] . w1W[o, :100] + w1b[o] -------------
__global__ void k_posw(const float* __restrict__ pos, const float* __restrict__ w1W,
                       const float* __restrict__ w1b) {
    int gw   = (blockIdx.x * blockDim.x + threadIdx.x) >> 5;
    int lane = threadIdx.x & 31;
    if (gw >= L * EMB) return;
    int l = gw / EMB, o = gw % EMB;
    const float* wr = w1W + o * 2 * EMB;
    float acc = 0.f;
    for (int k = lane; k < EMB; k += 32) acc += pos[l * EMB + k] * wr[k];
    acc = wredsum(acc);
    if (lane == 0) g_posw[l * EMB + o] = acc + w1b[o];
}

// ---------------- 5. GAT per batch element (padded shared) -------------------
__global__ void k_gat(const int* __restrict__ items, const int* __restrict__ adj,
                      const float* __restrict__ a0, const float* __restrict__ a1,
                      const float* __restrict__ a2, const float* __restrict__ a3) {
    __shared__ float sh[NN][EMB + 1];
    __shared__ float sa[4][EMB + 1];
    __shared__ float se[NN][NN];
    __shared__ int   sit[NN];
    int b = blockIdx.x, t = threadIdx.x, nt = blockDim.x;
    for (int i = t; i < NN; i += nt) sit[i] = items[b * NN + i];
    for (int i = t; i < EMB; i += nt) {
        sa[0][i] = a0[i]; sa[1][i] = a1[i]; sa[2][i] = a2[i]; sa[3][i] = a3[i];
    }
    __syncthreads();
    for (int p = t; p < NN * EMB; p += nt)
        sh[p / EMB][p % EMB] = g_e1t[sit[p / EMB] * EMB + p % EMB];
    __syncthreads();
    for (int p = t; p < NN * NN; p += nt) {
        int i = p / NN, j = p % NN;
        int av = adj[b * NN * NN + p];
        float ev;
        if (av >= 1 && av <= 4) {
            const float* ak = sa[av - 1];
            float acc = 0.f;
            #pragma unroll 4
            for (int d = 0; d < EMB; d++) acc += sh[i][d] * ak[d] * sh[j][d];
            ev = acc > 0.f ? acc : 0.2f * acc;
        } else ev = -9e15f;
        se[i][j] = ev;
    }
    __syncthreads();
    int w = t >> 5, lane = t & 31, nw = nt >> 5;
    for (int i = w; i < NN; i += nw) {
        float m = -INFINITY;
        for (int j = lane; j < NN; j += 32) m = fmaxf(m, se[i][j]);
        m = wredmax(m);
        float s = 0.f;
        for (int j = lane; j < NN; j += 32) { float ex = expf(se[i][j] - m); se[i][j] = ex; s += ex; }
        s = wredsum(s);
        float inv = 1.f / s;
        for (int j = lane; j < NN; j += 32) se[i][j] *= inv;
    }
    __syncthreads();
    for (int p = t; p < NN * EMB; p += nt) {
        int i = p / EMB, d = p % EMB;
        float acc = 0.f;
        #pragma unroll 5
        for (int j = 0; j < NN; j++) acc += se[i][j] * sh[j][d];
        g_h[b * NN * EMB + p] = acc;
    }
}

// ---------------- 6. get_seq + hs ---------------------------------------------
__global__ void k_seq(const int* __restrict__ rev, const int* __restrict__ alias,
                      const float* __restrict__ slen) {
    __shared__ float ss[L][EMB];
    int b = blockIdx.x, t = threadIdx.x, nt = blockDim.x;
    for (int p = t; p < L * EMB; p += nt) {
        int l = p / EMB, d = p % EMB;
        int r  = rev[b * L + l];
        int al = alias[b * L + l];
        float v = 0.2f * g_e1t[r * EMB + d] + 0.8f * g_h[(b * NN + al) * EMB + d];
        ss[l][d] = v;
        g_seq[b * L * EMB + p] = v;
    }
    __syncthreads();
    float sl = slen[b];
    for (int d = t; d < EMB; d += nt) {
        float a = 0.f;
        #pragma unroll 5
        for (int l = 0; l < L; l++) a += ss[l][d];
        g_hs[b * EMB + d] = a / sl;
    }
}

// ---------------- 7. soft attention -> sel ------------------------------------
__global__ void k_attn(const float* __restrict__ w1W,
                       const float* __restrict__ g1W, const float* __restrict__ g1b,
                       const float* __restrict__ g2W, const float* __restrict__ w2,
                       const int* __restrict__ mask) {
    __shared__ float ss [L][EMB + 1];
    __shared__ float snh[L][EMB + 1];
    __shared__ float sgh[EMB];
    __shared__ float shsv[EMB];
    __shared__ float sbeta[L];
    int b = blockIdx.x, t = threadIdx.x, nt = blockDim.x;
    int w = t >> 5, lane = t & 31, nw = nt >> 5;
    for (int p = t; p < L * EMB; p += nt) ss[p / EMB][p % EMB] = g_seq[b * L * EMB + p];
    for (int d = t; d < EMB; d += nt) shsv[d] = g_hs[b * EMB + d];
    for (int l = t; l < L; l += nt) sbeta[l] = 0.f;
    __syncthreads();
    for (int o = w; o < EMB; o += nw) {
        float acc = 0.f;
        for (int d = lane; d < EMB; d += 32) acc += shsv[d] * g2W[o * EMB + d];
        acc = wredsum(acc);
        if (lane == 0) sgh[o] = acc;
    }
    for (int p = t; p < L * EMB; p += nt) {
        int o = p / L, l = p % L;
        const float* wr = w1W + o * 2 * EMB + EMB;
        float acc = g_posw[l * EMB + o];
        #pragma unroll 4
        for (int k = 0; k < EMB; k++) acc += ss[l][k] * wr[k];
        snh[l][o] = tanhf(acc);
    }
    __syncthreads();
    for (int p = t; p < L * EMB; p += nt) {
        int o = p / L, l = p % L;
        float acc = g1b[o] + sgh[o];
        const float* wr = g1W + o * EMB;
        #pragma unroll 4
        for (int k = 0; k < EMB; k++) acc += snh[l][k] * wr[k];
        float s = 1.f / (1.f + expf(-acc));
        atomicAdd(&sbeta[l], s * w2[o]);
    }
    __syncthreads();
    for (int l = t; l < L; l += nt) sbeta[l] *= (float)mask[b * L + l];
    __syncthreads();
    for (int d = t; d < EMB; d += nt) {
        float acc = 0.f;
        #pragma unroll 5
        for (int l = 0; l < L; l++) acc += sbeta[l] * ss[l][d];
        g_sel[b * EMB + d] = acc;
    }
}

// ---------------- 8a. session conv 1: g_s1 = A @ g_sel -------------------------
__global__ void k_sessmm1(const float* __restrict__ A) {
    __shared__ float sadj[B];
    int b = blockIdx.x, t = threadIdx.x, nt = blockDim.x;
    for (int j = t; j < B; j += nt) sadj[j] = A[b * B + j];
    __syncthreads();
    for (int d = t; d < EMB; d += nt) {
        float acc = 0.f;
        #pragma unroll 4
        for (int j = 0; j < B; j++) acc += sadj[j] * g_sel[j * EMB + d];
        g_s1[b * EMB + d] = acc;
    }
}

// ---------------- 8b. session conv 2 fused with l2norm combine -> g_self ------
__global__ void k_sessmm2c(const float* __restrict__ A, const float* __restrict__ aw) {
    __shared__ float sadj[B];
    __shared__ float red0[128], red1[128], red2[128];
    int b = blockIdx.x, t = threadIdx.x;
    for (int j = t; j < B; j += 128) sadj[j] = A[b * B + j];
    __syncthreads();
    float s2v = 0.f, selv = 0.f, s1v = 0.f;
    if (t < EMB) {
        float acc = 0.f;
        #pragma unroll 4
        for (int j = 0; j < B; j++) acc += sadj[j] * g_s1[j * EMB + t];
        s2v  = acc;
        selv = g_sel[b * EMB + t];
        s1v  = g_s1[b * EMB + t];
    }
    red0[t] = selv * selv; red1[t] = s1v * s1v; red2[t] = s2v * s2v;
    __syncthreads();
    for (int o = 64; o; o >>= 1) {
        if (t < o) { red0[t] += red0[t + o]; red1[t] += red1[t + o]; red2[t] += red2[t + o]; }
        __syncthreads();
    }
    float i0 = aw[0] / fmaxf(sqrtf(red0[0]), 1e-12f);
    float i1 = aw[1] / fmaxf(sqrtf(red1[0]), 1e-12f);
    float i2 = aw[2] / fmaxf(sqrtf(red2[0]), 1e-12f);
    if (t < EMB) g_self[b * EMB + t] = selv * i0 + s1v * i1 + s2v * i2;
}

// ---------------- 9. scores: 4x4 register-tiled f32x2 GEMM --------------------
#define SBT 64
#define SNT 128
#define NBX ((N_NODE + SNT - 1) / SNT)   // 313 (last block partial)
#define SA_STRIDE (EMB + 1)
#define SB_STRIDE (SNT + 2)
#define SCORE_SMEM (SBT * SA_STRIDE * 8 + EMB * SB_STRIDE * 4)   // ~104 KB

__global__ void k_scores(float* __restrict__ sc) {
    extern __shared__ char smraw[];
    float2* sA2 = (float2*)smraw;                                  // [SBT][EMB+1] dup {a,a}
    float*  sB  = (float*)(smraw + SBT * SA_STRIDE * sizeof(float2)); // [EMB][SNT+2]
    int bn = blockIdx.x * SNT;
    int bb = blockIdx.y * SBT;
    int t = threadIdx.x;                    // 256
    for (int p = t; p < SBT * EMB; p += 256) {
        int r = p / EMB, c = p % EMB;
        float v = 4.f * g_self[(bb + r) * EMB + c];
        sA2[r * SA_STRIDE + c] = make_float2(v, v);
    }
    for (int p = t; p < SNT * EMB; p += 256) {
        int r = p / EMB, c = p % EMB;       // r = local col, c = k
        int n = bn + r;
        sB[c * SB_STRIDE + r] = (n < N_NODE) ? g_e1t[(n + 1) * EMB + c] : 0.f;
    }
    __syncthreads();
    int tx = t & 15, ty = t >> 4;
    unsigned long long acc[4][4];
    #pragma unroll
    for (int i = 0; i < 4; i++)
        #pragma unroll
        for (int j = 0; j < 4; j++) acc[i][j] = 0ull;
    #pragma unroll 2
    for (int k = 0; k < EMB; k++) {
        unsigned long long a0 = *(const unsigned long long*)&sA2[(ty     ) * SA_STRIDE + k];
        unsigned long long a1 = *(const unsigned long long*)&sA2[(ty + 16) * SA_STRIDE + k];
        unsigned long long a2 = *(const unsigned long long*)&sA2[(ty + 32) * SA_STRIDE + k];
        unsigned long long a3 = *(const unsigned long long*)&sA2[(ty + 48) * SA_STRIDE + k];
        const float* bk = sB + k * SB_STRIDE;
        unsigned long long b0 = *(const unsigned long long*)&bk[2 * tx];
        unsigned long long b1 = *(const unsigned long long*)&bk[2 * tx + 32];
        unsigned long long b2 = *(const unsigned long long*)&bk[2 * tx + 64];
        unsigned long long b3 = *(const unsigned long long*)&bk[2 * tx + 96];
        asm("fma.rn.f32x2 %0, %1, %2, %0;" : "+l"(acc[0][0]) : "l"(a0), "l"(b0));
        asm("fma.rn.f32x2 %0, %1, %2, %0;" : "+l"(acc[0][1]) : "l"(a0), "l"(b1));
        asm("fma.rn.f32x2 %0, %1, %2, %0;" : "+l"(acc[0][2]) : "l"(a0), "l"(b2));
        asm("fma.rn.f32x2 %0, %1, %2, %0;" : "+l"(acc[0][3]) : "l"(a0), "l"(b3));
        asm("fma.rn.f32x2 %0, %1, %2, %0;" : "+l"(acc[1][0]) : "l"(a1), "l"(b0));
        asm("fma.rn.f32x2 %0, %1, %2, %0;" : "+l"(acc[1][1]) : "l"(a1), "l"(b1));
        asm("fma.rn.f32x2 %0, %1, %2, %0;" : "+l"(acc[1][2]) : "l"(a1), "l"(b2));
        asm("fma.rn.f32x2 %0, %1, %2, %0;" : "+l"(acc[1][3]) : "l"(a1), "l"(b3));
        asm("fma.rn.f32x2 %0, %1, %2, %0;" : "+l"(acc[2][0]) : "l"(a2), "l"(b0));
        asm("fma.rn.f32x2 %0, %1, %2, %0;" : "+l"(acc[2][1]) : "l"(a2), "l"(b1));
        asm("fma.rn.f32x2 %0, %1, %2, %0;" : "+l"(acc[2][2]) : "l"(a2), "l"(b2));
        asm("fma.rn.f32x2 %0, %1, %2, %0;" : "+l"(acc[2][3]) : "l"(a2), "l"(b3));
        asm("fma.rn.f32x2 %0, %1, %2, %0;" : "+l"(acc[3][0]) : "l"(a3), "l"(b0));
        asm("fma.rn.f32x2 %0, %1, %2, %0;" : "+l"(acc[3][1]) : "l"(a3), "l"(b1));
        asm("fma.rn.f32x2 %0, %1, %2, %0;" : "+l"(acc[3][2]) : "l"(a3), "l"(b2));
        asm("fma.rn.f32x2 %0, %1, %2, %0;" : "+l"(acc[3][3]) : "l"(a3), "l"(b3));
    }
    #pragma unroll
    for (int i = 0; i < 4; i++) {
        size_t rowb = (size_t)(bb + ty + 16 * i) * N_NODE + bn;
        #pragma unroll
        for (int j = 0; j < 4; j++) {
            int col = 2 * tx + 32 * j;
            if (bn + col < N_NODE)
                *reinterpret_cast<float2*>(sc + rowb + col) =
                    *reinterpret_cast<float2*>(&acc[i][j]);
        }
    }
}

// ---------------- 10. per-row LSE (online) + re-zero g_cnt --------------------
__global__ void k_lse(const float* __restrict__ sc) {
    int b = blockIdx.x, t = threadIdx.x, nt = blockDim.x;
    const float2* row = reinterpret_cast<const float2*>(sc + (size_t)b * N_NODE);
    float m = -INFINITY, s = 0.f;
    for (int i = t; i < N_NODE / 2; i += nt) {
        float2 v = row[i];
        float mv = fmaxf(v.x, v.y);
        if (mv > m) { s *= expf(m - mv); m = mv; }
        s += expf(v.x - m) + expf(v.y - m);
    }
    #pragma unroll
    for (int o = 16; o; o >>= 1) {
        float mo = __shfl_xor_sync(FULLM, m, o);
        float so = __shfl_xor_sync(FULLM, s, o);
        float mn = fmaxf(m, mo);
        s = s * expf(m - mn) + so * expf(mo - mn);
        m = mn;
    }
    __shared__ float sm[8], sv[8];
    if ((t & 31) == 0) { sm[t >> 5] = m; sv[t >> 5] = s; }
    __syncthreads();
    if (t == 0) {
        float M = sm[0], S = sv[0];
        for (int w = 1; w < nt / 32; w++) {
            float mn = fmaxf(M, sm[w]);
            S = S * expf(M - mn) + sv[w] * expf(sm[w] - mn);
            M = mn;
        }
        g_lse[b] = M + logf(S);
    }
    int gid = b * nt + t;
    if (gid < N_NODE) g_cnt[gid] = 0;
}

// ---------------- 11. loss -----------------------------------------------------
__global__ void k_loss(const float* __restrict__ sc, const int* __restrict__ tar,
                       float* __restrict__ out, int off) {
    int t = threadIdx.x;
    float v = sc[(size_t)t * N_NODE + tar[t]] - g_lse[t];
    v = wredsum(v);
    __shared__ float sp[16];
    if ((t & 31) == 0) sp[t >> 5] = v;
    __syncthreads();
    if (t == 0) {
        float tot = 0.f;
        for (int w = 0; w < 16; w++) tot += sp[w];
        float loss = -tot / (float)B;
        if (off >= 2)      { out[0] = 0.f; out[1] = loss; }
        else if (off == 1) { out[0] = loss; }
    }
}

// ---------------- host launcher ------------------------------------------------
extern "C" void kernel_launch(void* const* d_in, const int* in_sizes, int n_in,
                              void* d_out, int out_size) {
    int sh = (n_in >= 6 && in_sizes[5] == 1) ? 0 : -1;

    const int*   tar   = (const int*  )d_in[0];
    const int*   rev   = (const int*  )d_in[1];
    const int*   mask  = (const int*  )d_in[2];
    const float* slen  = (const float*)d_in[3];
    const float* sadj  = (const float*)d_in[4];
    const int*   items = (const int*  )d_in[6 + sh];
    const int*   adj   = (const int*  )d_in[7 + sh];
    const int*   alias = (const int*  )d_in[8 + sh];
    const int*   rows  = (const int*  )d_in[9 + sh];
    const int*   cols  = (const int*  )d_in[10 + sh];
    const float* vals  = (const float*)d_in[11 + sh];
    const float* nemb  = (const float*)d_in[12 + sh];
    const float* bit   = (const float*)d_in[13 + sh];
    const float* asess = (const float*)d_in[14 + sh];
    const float* a0    = (const float*)d_in[15 + sh];
    const float* a1    = (const float*)d_in[16 + sh];
    const float* a2    = (const float*)d_in[17 + sh];
    const float* a3    = (const float*)d_in[18 + sh];
    const float* w1W   = (const float*)d_in[19 + sh];
    const float* w1b   = (const float*)d_in[20 + sh];
    const float* w2    = (const float*)d_in[21 + sh];
    const float* g1W   = (const float*)d_in[22 + sh];
    const float* g1b   = (const float*)d_in[23 + sh];
    const float* g2W   = (const float*)d_in[24 + sh];
    const float* pos   = (const float*)d_in[25 + sh];

    float* outf = (float*)d_out;
    int off = out_size - B * N_NODE;
    if (off < 0) off = 0;
    float* scores = outf + off;

    static int smem_set = 0;
    if (!smem_set) {
        cudaFuncSetAttribute(k_scores, cudaFuncAttributeMaxDynamicSharedMemorySize,
                             SCORE_SMEM);
        smem_set = 1;
    }

    k_hist<<<(E_EDGES + 255) / 256, 256>>>(rows);
    k_scan<<<1, NT_SCAN>>>();
    k_scatter<<<(E_EDGES + 255) / 256, 256>>>(rows, cols, vals);
    k_spmm_csr1<<<(N_NODE * 32 + 255) / 256, 256>>>(nemb);
    k_spmm_csr2<<<(N_NODE * 32 + 255) / 256, 256>>>();
    k_combine_item<<<(N_NODE * 32 + 255) / 256, 256>>>(nemb, bit);
    k_posw<<<(L * EMB * 32 + 255) / 256, 256>>>(pos, w1W, w1b);
    k_gat<<<B, 256>>>(items, adj, a0, a1, a2, a3);
    k_seq<<<B, 128>>>(rev, alias, slen);
    k_attn<<<B, 256>>>(w1W, g1W, g1b, g2W, w2, mask);
    k_sessmm1<<<B, 128>>>(sadj);
    k_sessmm2c<<<B, 128>>>(sadj, asess);
    k_scores<<<dim3(NBX, B / SBT), 256, SCORE_SMEM>>>(scores);
    k_lse<<<B, 256>>>(scores);
    k_loss<<<1, 512>>>(scores, tar, outf, off);
}